// round 1
// baseline (speedup 1.0000x reference)
#include <cuda_runtime.h>
#include <cuda_bf16.h>

#define NN 10000
#define NE 320000
#define NH 128
#define TS_STRIDE 129   // padded smem stride: 129 mod 32 == 1 -> conflict-free transpose

// Scratch (allocation-free rule: __device__ globals)
__device__ float g_hw[(size_t)NN * NH];
__device__ float g_x[(size_t)NN * NH];   // used as agg accumulator, then relu'd in place

// ---------------------------------------------------------------------------
// zero the aggregation buffer
__global__ void zero_x_kernel() {
    int i = blockIdx.x * 256 + threadIdx.x;
    if (i < NN * NH) g_x[i] = 0.0f;
}

// ---------------------------------------------------------------------------
// Load a 128-row x 128-col tile of a row-major [rows][128] matrix into SMEM
// TRANSPOSED: Ts[k][m] at Ts[k*TS_STRIDE + m]. Lane walks k (coalesced 128B
// global loads), store addresses step TS_STRIDE per lane -> 32 distinct banks.
__device__ __forceinline__ void load_tileT(const float* __restrict__ src,
                                           int row0, int maxrows,
                                           float* __restrict__ Ts) {
    int lane = threadIdx.x & 31;
    int w    = threadIdx.x >> 5;           // 8 warps, 16 rows each
    #pragma unroll
    for (int rr = 0; rr < 16; ++rr) {
        int r    = w * 16 + rr;
        int grow = row0 + r;
        bool ok  = (grow < maxrows);
        const float* p = src + (size_t)grow * NH;
        #pragma unroll
        for (int q = 0; q < 4; ++q) {
            int k = lane + 32 * q;
            Ts[k * TS_STRIDE + r] = ok ? p[k] : 0.0f;
        }
    }
}

// Load a row-major 128x128 matrix (W) into SMEM as Ws[k][n], stride 129.
__device__ __forceinline__ void load_tile_rowmajor(const float* __restrict__ src,
                                                   float* __restrict__ Ts) {
    int lane = threadIdx.x & 31;
    int w    = threadIdx.x >> 5;
    #pragma unroll
    for (int rr = 0; rr < 16; ++rr) {
        int k = w * 16 + rr;
        #pragma unroll
        for (int q = 0; q < 4; ++q) {
            int n = lane + 32 * q;
            Ts[k * TS_STRIDE + n] = src[k * NH + n];
        }
    }
}

// ---------------------------------------------------------------------------
// Shared 8x8-microtile FMA core. As/Bs are [k][*] stride-129.
// Thread (tx,ty) owns rows m = ty+16i, cols n = tx+16j (strided microtile ->
// scalar LDS, conflict-free broadcasts).
__device__ __forceinline__ void mma_core(const float* __restrict__ As,
                                         const float* __restrict__ Bs,
                                         int tx, int ty, float acc[8][8]) {
    #pragma unroll 8
    for (int k = 0; k < 128; ++k) {
        float a[8], b[8];
        #pragma unroll
        for (int i = 0; i < 8; ++i) a[i] = As[k * TS_STRIDE + ty + 16 * i];
        #pragma unroll
        for (int j = 0; j < 8; ++j) b[j] = Bs[k * TS_STRIDE + tx + 16 * j];
        #pragma unroll
        for (int i = 0; i < 8; ++i)
            #pragma unroll
            for (int j = 0; j < 8; ++j)
                acc[i][j] = fmaf(a[i], b[j], acc[i][j]);
    }
}

// ---------------------------------------------------------------------------
// hw = h @ W   (10000x128 @ 128x128). One block per 128-row stripe.
extern "C" __global__ void gemm_hw_kernel(const float* __restrict__ h,
                                          const float* __restrict__ W) {
    extern __shared__ float smem[];
    float* As = smem;                       // h tile, transposed [k][m]
    float* Bs = smem + 128 * TS_STRIDE;     // W, [k][n]
    int row0 = blockIdx.x * 128;

    load_tileT(h, row0, NN, As);
    load_tile_rowmajor(W, Bs);
    __syncthreads();

    int tx = threadIdx.x & 15, ty = threadIdx.x >> 4;
    float acc[8][8] = {};
    mma_core(As, Bs, tx, ty, acc);

    #pragma unroll
    for (int i = 0; i < 8; ++i) {
        int m = row0 + ty + 16 * i;
        if (m < NN) {
            #pragma unroll
            for (int j = 0; j < 8; ++j)
                g_hw[(size_t)m * NH + tx + 16 * j] = acc[i][j];
        }
    }
}

// ---------------------------------------------------------------------------
// Edge scatter: agg[dst] += hw[src]. One thread per (edge, channel).
// Warp = 32 consecutive channels of one edge -> coalesced load + coalesced RED.
extern "C" __global__ void scatter_add_kernel(const int* __restrict__ es,
                                              const int* __restrict__ ed) {
    int idx = blockIdx.x * 256 + threadIdx.x;   // < 40,960,000
    int e = idx >> 7;
    int c = idx & 127;
    int s = es[e];
    int d = ed[e];
    atomicAdd(&g_x[(size_t)d * NH + c], g_hw[(size_t)s * NH + c]);
}

// ---------------------------------------------------------------------------
// x = relu(agg + b), in place
extern "C" __global__ void relu_bias_kernel(const float* __restrict__ b) {
    int i = blockIdx.x * 256 + threadIdx.x;
    if (i < NN * NH) {
        float v = g_x[i] + b[i & 127];
        g_x[i] = v > 0.0f ? v : 0.0f;
    }
}

// ---------------------------------------------------------------------------
// out = x @ x^T, symmetric: compute only tiles bx >= by, mirror via SMEM
// transpose stage so both stores stay coalesced.
extern "C" __global__ void gemm_xxt_kernel(float* __restrict__ out) {
    int bxn = blockIdx.x;   // column block
    int bym = blockIdx.y;   // row block
    if (bxn < bym) return;  // lower triangle handled by mirror

    extern __shared__ float smem[];
    float* As = smem;                       // rows tile, [k][m]
    float* Bs = smem + 128 * TS_STRIDE;     // cols tile, [k][n]

    load_tileT(g_x, bym * 128, NN, As);
    load_tileT(g_x, bxn * 128, NN, Bs);
    __syncthreads();

    int tx = threadIdx.x & 15, ty = threadIdx.x >> 4;
    float acc[8][8] = {};
    mma_core(As, Bs, tx, ty, acc);

    // direct store: C[m][n] — lanes vary tx -> consecutive n, coalesced
    #pragma unroll
    for (int i = 0; i < 8; ++i) {
        int m = bym * 128 + ty + 16 * i;
        if (m < NN) {
            #pragma unroll
            for (int j = 0; j < 8; ++j) {
                int n = bxn * 128 + tx + 16 * j;
                if (n < NN) out[(size_t)m * NN + n] = acc[i][j];
            }
        }
    }

    // mirror store C[n][m]: stage transpose in SMEM, then write coalesced rows
    if (bxn != bym) {
        __syncthreads();
        float* Tr = As;  // reuse (128 x 129 floats fits in As+start of Bs region)
        #pragma unroll
        for (int j = 0; j < 8; ++j)
            #pragma unroll
            for (int i = 0; i < 8; ++i)
                Tr[(tx + 16 * j) * TS_STRIDE + (ty + 16 * i)] = acc[i][j];
        __syncthreads();

        #pragma unroll 4
        for (int it = 0; it < 64; ++it) {
            int lin = it * 256 + threadIdx.x;
            int ln = lin >> 7;          // local n (row of mirrored tile)
            int lm = lin & 127;         // local m (col of mirrored tile)
            int n = bxn * 128 + ln;
            int m = bym * 128 + lm;
            if (n < NN && m < NN)
                out[(size_t)n * NN + m] = Tr[ln * TS_STRIDE + lm];
        }
    }
}

// ---------------------------------------------------------------------------
extern "C" void kernel_launch(void* const* d_in, const int* in_sizes, int n_in,
                              void* d_out, int out_size) {
    const float* h  = (const float*)d_in[0];
    const float* W  = (const float*)d_in[1];
    const float* b  = (const float*)d_in[2];
    const int*   es = (const int*)d_in[3];
    const int*   ed = (const int*)d_in[4];
    float*       out = (float*)d_out;

    const size_t smembytes = (size_t)2 * 128 * TS_STRIDE * sizeof(float); // 132096 B

    // Sticky per-process attributes; idempotent, not a stream op.
    cudaFuncSetAttribute(gemm_hw_kernel,
                         cudaFuncAttributeMaxDynamicSharedMemorySize, (int)smembytes);
    cudaFuncSetAttribute(gemm_xxt_kernel,
                         cudaFuncAttributeMaxDynamicSharedMemorySize, (int)smembytes);

    zero_x_kernel<<<(NN * NH + 255) / 256, 256>>>();
    gemm_hw_kernel<<<(NN + 127) / 128, 256, smembytes>>>(h, W);
    scatter_add_kernel<<<(NE * NH) / 256, 256>>>(es, ed);
    relu_bias_kernel<<<(NN * NH + 255) / 256, 256>>>(b);

    dim3 grid((NN + 127) / 128, (NN + 127) / 128);  // 79 x 79, lower tri exits
    gemm_xxt_kernel<<<grid, 256, smembytes>>>(out);
}

// round 3
// speedup vs baseline: 1.6430x; 1.6430x over previous
#include <cuda_runtime.h>
#include <cuda_bf16.h>
#include <cstdint>

#define NN 10000
#define NE 320000
#define NH 128
#define NPAD 10112            // 79 * 128, zero-padded rows
#define TS_STRIDE 129         // f32 stage stride
#define XT_STRIDE 136         // bf16 tile stride: 272B/row == 16 mod 128 -> conflict-free frags

// ---------------- scratch (__device__ globals: allocation-free rule) --------
__device__ float g_hw[(size_t)NN * NH];
__device__ float g_x[(size_t)NN * NH];                 // scatter accumulator
__device__ __nv_bfloat16 g_xhi[(size_t)NPAD * NH];
__device__ __nv_bfloat16 g_xlo[(size_t)NPAD * NH];

// ============================================================================
// 1) zero accumulator
__global__ void zero_x_kernel() {
    int i = blockIdx.x * 256 + threadIdx.x;
    if (i < NN * NH) g_x[i] = 0.0f;
}

// ============================================================================
// 2) hw = h @ W (fp32 SIMT, 0.33 GFLOP — negligible)
__device__ __forceinline__ void load_tileT(const float* __restrict__ src,
                                           int row0, int maxrows,
                                           float* __restrict__ Ts) {
    int lane = threadIdx.x & 31, w = threadIdx.x >> 5;
    #pragma unroll
    for (int rr = 0; rr < 16; ++rr) {
        int r = w * 16 + rr;
        bool ok = (row0 + r < maxrows);
        const float* p = src + (size_t)(row0 + r) * NH;
        #pragma unroll
        for (int q = 0; q < 4; ++q) {
            int k = lane + 32 * q;
            Ts[k * TS_STRIDE + r] = ok ? p[k] : 0.0f;
        }
    }
}
__device__ __forceinline__ void load_tile_rowmajor(const float* __restrict__ src,
                                                   float* __restrict__ Ts) {
    int lane = threadIdx.x & 31, w = threadIdx.x >> 5;
    #pragma unroll
    for (int rr = 0; rr < 16; ++rr) {
        int k = w * 16 + rr;
        #pragma unroll
        for (int q = 0; q < 4; ++q) {
            int n = lane + 32 * q;
            Ts[k * TS_STRIDE + n] = src[k * NH + n];
        }
    }
}
extern "C" __global__ void gemm_hw_kernel(const float* __restrict__ h,
                                          const float* __restrict__ W) {
    extern __shared__ float smemf[];
    float* As = smemf;
    float* Bs = smemf + 128 * TS_STRIDE;
    int row0 = blockIdx.x * 128;
    load_tileT(h, row0, NN, As);
    load_tile_rowmajor(W, Bs);
    __syncthreads();
    int tx = threadIdx.x & 15, ty = threadIdx.x >> 4;
    float acc[8][8] = {};
    #pragma unroll 8
    for (int k = 0; k < 128; ++k) {
        float a[8], b[8];
        #pragma unroll
        for (int i = 0; i < 8; ++i) a[i] = As[k * TS_STRIDE + ty + 16 * i];
        #pragma unroll
        for (int j = 0; j < 8; ++j) b[j] = Bs[k * TS_STRIDE + tx + 16 * j];
        #pragma unroll
        for (int i = 0; i < 8; ++i)
            #pragma unroll
            for (int j = 0; j < 8; ++j)
                acc[i][j] = fmaf(a[i], b[j], acc[i][j]);
    }
    #pragma unroll
    for (int i = 0; i < 8; ++i) {
        int m = row0 + ty + 16 * i;
        if (m < NN)
            #pragma unroll
            for (int j = 0; j < 8; ++j)
                g_hw[(size_t)m * NH + tx + 16 * j] = acc[i][j];
    }
}

// ============================================================================
// 3) scatter: g_x[dst] += g_hw[src]; float4 loads, scalar atomics
extern "C" __global__ void scatter_add_kernel(const int* __restrict__ es,
                                              const int* __restrict__ ed) {
    int idx = blockIdx.x * 256 + threadIdx.x;   // NE * 32 threads
    int e  = idx >> 5;
    int c4 = (idx & 31) << 2;
    int s = es[e], d = ed[e];
    float4 v = *(const float4*)&g_hw[(size_t)s * NH + c4];
    float* dst = &g_x[(size_t)d * NH + c4];
    atomicAdd(dst + 0, v.x);
    atomicAdd(dst + 1, v.y);
    atomicAdd(dst + 2, v.z);
    atomicAdd(dst + 3, v.w);
}

// ============================================================================
// 4) x = relu(agg + b); split into bf16 hi/lo; zero padded rows
extern "C" __global__ void relu_bias_convert_kernel(const float* __restrict__ b) {
    int i = blockIdx.x * 256 + threadIdx.x;
    if (i < NPAD * NH) {
        float v = 0.0f;
        if (i < NN * NH) {
            v = g_x[i] + b[i & 127];
            v = v > 0.0f ? v : 0.0f;
        }
        __nv_bfloat16 hi = __float2bfloat16(v);
        float r = v - __bfloat162float(hi);
        g_xhi[i] = hi;
        g_xlo[i] = __float2bfloat16(r);
    }
}

// ============================================================================
// 5) out = x @ x^T via HMMA (mma.sync m16n8k16 bf16), hi/lo 3-split,
//    symmetric tiles (upper triangle + mirrored store).
//
// SMEM tiles: 4x [128 rows x XT_STRIDE bf16] (A_hi, A_lo, B_hi, B_lo).
#define TILE_BYTES (128 * XT_STRIDE * 2)            // 34816
#define SMEM_XXT_BYTES (4 * TILE_BYTES)             // 139264

__device__ __forceinline__ void load_bf16_tile_pad(const __nv_bfloat16* __restrict__ src,
                                                   int row0, char* __restrict__ dst) {
    int tid = threadIdx.x;  // 256 threads
    #pragma unroll
    for (int it = 0; it < 8; ++it) {
        int chunk = it * 256 + tid;        // 0..2047 (16B chunks: 16 per row)
        int row   = chunk >> 4;
        int c16   = chunk & 15;
        uint4 v = *(const uint4*)(src + (size_t)(row0 + row) * NH + c16 * 8);
        *(uint4*)(dst + row * (XT_STRIDE * 2) + c16 * 16) = v;
    }
}

__device__ __forceinline__ void mma_bf16(float d[4], uint32_t a0, uint32_t a1,
                                         uint32_t a2, uint32_t a3,
                                         uint32_t b0, uint32_t b1) {
    asm volatile(
        "mma.sync.aligned.m16n8k16.row.col.f32.bf16.bf16.f32 "
        "{%0,%1,%2,%3}, {%4,%5,%6,%7}, {%8,%9}, {%0,%1,%2,%3};"
        : "+f"(d[0]), "+f"(d[1]), "+f"(d[2]), "+f"(d[3])
        : "r"(a0), "r"(a1), "r"(a2), "r"(a3), "r"(b0), "r"(b1));
}

extern "C" __global__ void __launch_bounds__(256, 1)
xxt_mma_kernel(float* __restrict__ out) {
    int bxn = blockIdx.x, bym = blockIdx.y;
    if (bxn < bym) return;   // lower triangle via mirror

    extern __shared__ char smem[];
    char* Ahi = smem;
    char* Alo = smem + TILE_BYTES;
    char* Bhi = smem + 2 * TILE_BYTES;
    char* Blo = smem + 3 * TILE_BYTES;

    load_bf16_tile_pad(g_xhi, bym * 128, Ahi);
    load_bf16_tile_pad(g_xlo, bym * 128, Alo);
    load_bf16_tile_pad(g_xhi, bxn * 128, Bhi);
    load_bf16_tile_pad(g_xlo, bxn * 128, Blo);
    __syncthreads();

    int tid = threadIdx.x, lane = tid & 31, wid = tid >> 5;
    int wm = wid & 1;        // 0..1 -> 64 rows each
    int wn = wid >> 1;       // 0..3 -> 32 cols each
    int frow = lane >> 2;    // fragment row/col within 8
    int fcol = 2 * (lane & 3);

    float acc[4][4][4] = {};

    const char* APASS[3] = {Ahi, Ahi, Alo};
    const char* BPASS[3] = {Bhi, Blo, Bhi};

    #pragma unroll
    for (int p = 0; p < 3; ++p) {
        const char* Ab = APASS[p];
        const char* Bb = BPASS[p];
        #pragma unroll
        for (int k0 = 0; k0 < 8; ++k0) {
            int kc = 16 * k0 + fcol;       // bf16 col of low half
            uint32_t a[4][4], b[4][2];
            #pragma unroll
            for (int i = 0; i < 4; ++i) {
                int r = wm * 64 + i * 16 + frow;
                const char* base = Ab + r * (XT_STRIDE * 2) + kc * 2;
                a[i][0] = *(const uint32_t*)(base);
                a[i][1] = *(const uint32_t*)(base + 8 * (XT_STRIDE * 2));
                a[i][2] = *(const uint32_t*)(base + 16);
                a[i][3] = *(const uint32_t*)(base + 8 * (XT_STRIDE * 2) + 16);
            }
            #pragma unroll
            for (int j = 0; j < 4; ++j) {
                int n = wn * 32 + j * 8 + frow;
                const char* base = Bb + n * (XT_STRIDE * 2) + kc * 2;
                b[j][0] = *(const uint32_t*)(base);
                b[j][1] = *(const uint32_t*)(base + 16);
            }
            #pragma unroll
            for (int i = 0; i < 4; ++i)
                #pragma unroll
                for (int j = 0; j < 4; ++j)
                    mma_bf16(acc[i][j], a[i][0], a[i][1], a[i][2], a[i][3],
                             b[j][0], b[j][1]);
        }
    }
    __syncthreads();   // done reading tiles; reuse smem as f32 stage

    float* stage = (float*)smem;   // 128 x 129 f32 = 66048 B
    #pragma unroll
    for (int i = 0; i < 4; ++i) {
        int r = wm * 64 + i * 16 + frow;
        #pragma unroll
        for (int j = 0; j < 4; ++j) {
            int c = wn * 32 + j * 8 + fcol;
            stage[r * TS_STRIDE + c]           = acc[i][j][0];
            stage[r * TS_STRIDE + c + 1]       = acc[i][j][1];
            stage[(r + 8) * TS_STRIDE + c]     = acc[i][j][2];
            stage[(r + 8) * TS_STRIDE + c + 1] = acc[i][j][3];
        }
    }
    __syncthreads();

    int m0 = bym * 128, n0 = bxn * 128;
    int rsub = tid >> 5;          // 0..7
    int c = (tid & 31) << 2;      // 0..124 step 4

    // direct store C[m][n] (coalesced float4 rows)
    #pragma unroll 4
    for (int it = 0; it < 16; ++it) {
        int r = it * 8 + rsub;
        int m = m0 + r;
        if (m < NN) {
            float4 v;
            v.x = stage[r * TS_STRIDE + c];
            v.y = stage[r * TS_STRIDE + c + 1];
            v.z = stage[r * TS_STRIDE + c + 2];
            v.w = stage[r * TS_STRIDE + c + 3];
            if (n0 + c + 3 < NN) {
                *(float4*)&out[(size_t)m * NN + n0 + c] = v;
            } else {
                float vv[4] = {v.x, v.y, v.z, v.w};
                #pragma unroll
                for (int q = 0; q < 4; ++q)
                    if (n0 + c + q < NN) out[(size_t)m * NN + n0 + c + q] = vv[q];
            }
        }
    }

    // mirror store C[n][m] (transposed reads from stage, coalesced stores)
    if (bxn != bym) {
        #pragma unroll 4
        for (int it = 0; it < 16; ++it) {
            int r2 = it * 8 + rsub;        // local n
            int n = n0 + r2;
            if (n < NN) {
                float4 v;
                v.x = stage[(c)     * TS_STRIDE + r2];
                v.y = stage[(c + 1) * TS_STRIDE + r2];
                v.z = stage[(c + 2) * TS_STRIDE + r2];
                v.w = stage[(c + 3) * TS_STRIDE + r2];
                // bym <= 77 here -> m0 + c + 3 <= 9984+127 < NN, always valid
                *(float4*)&out[(size_t)n * NN + m0 + c] = v;
            }
        }
    }
}

// ============================================================================
extern "C" void kernel_launch(void* const* d_in, const int* in_sizes, int n_in,
                              void* d_out, int out_size) {
    const float* h  = (const float*)d_in[0];
    const float* W  = (const float*)d_in[1];
    const float* b  = (const float*)d_in[2];
    const int*   es = (const int*)d_in[3];
    const int*   ed = (const int*)d_in[4];
    float*       out = (float*)d_out;

    const size_t smem_hw = (size_t)2 * 128 * TS_STRIDE * sizeof(float);
    cudaFuncSetAttribute(gemm_hw_kernel,
                         cudaFuncAttributeMaxDynamicSharedMemorySize, (int)smem_hw);
    cudaFuncSetAttribute(xxt_mma_kernel,
                         cudaFuncAttributeMaxDynamicSharedMemorySize, SMEM_XXT_BYTES);

    zero_x_kernel<<<(NN * NH + 255) / 256, 256>>>();
    gemm_hw_kernel<<<(NN + 127) / 128, 256, smem_hw>>>(h, W);
    scatter_add_kernel<<<(NE * 32) / 256, 256>>>(es, ed);
    relu_bias_convert_kernel<<<(NPAD * NH + 255) / 256, 256>>>(b);

    dim3 grid(79, 79);
    xxt_mma_kernel<<<grid, 256, SMEM_XXT_BYTES>>>(out);
}

// round 4
// speedup vs baseline: 2.0306x; 1.2360x over previous
#include <cuda_runtime.h>
#include <cuda_bf16.h>
#include <cstdint>

#define NN 10000
#define NE 320000
#define NH 128
#define NPAD 10112            // 79 * 128, zero-padded rows
#define TS_STRIDE 129         // f32 stage stride
#define XT_STRIDE 136         // bf16 tile stride: 272B/row == 16 mod 128 -> conflict-free frags

// ---------------- scratch (__device__ globals: allocation-free rule) --------
__device__ float g_hw[(size_t)NN * NH];
__device__ __nv_bfloat16 g_xhi[(size_t)NPAD * NH];
__device__ __nv_bfloat16 g_xlo[(size_t)NPAD * NH];
__device__ int g_deg[NN];
__device__ int g_off[NN + 1];
__device__ int g_fill[NN];
__device__ int g_csr[NE];

// ============================================================================
// 0) zero CSR counters
__global__ void csr_zero_kernel() {
    int i = blockIdx.x * 256 + threadIdx.x;
    if (i < NN) { g_deg[i] = 0; g_fill[i] = 0; }
}

// 0b) count in-degree per dst
__global__ void csr_count_kernel(const int* __restrict__ ed) {
    int e = blockIdx.x * 256 + threadIdx.x;
    if (e < NE) atomicAdd(&g_deg[ed[e]], 1);
}

// 0c) exclusive prefix sum of degrees -> g_off (single block, 1024 threads)
__global__ void csr_scan_kernel() {
    __shared__ int part[1024];
    int tid = threadIdx.x;
    int base = tid * 10;                 // 1024*10 >= 10000
    int s = 0;
    #pragma unroll
    for (int q = 0; q < 10; ++q) {
        int i = base + q;
        if (i < NN) s += g_deg[i];
    }
    part[tid] = s;
    __syncthreads();
    #pragma unroll
    for (int off = 1; off < 1024; off <<= 1) {
        int v = (tid >= off) ? part[tid - off] : 0;
        __syncthreads();
        part[tid] += v;
        __syncthreads();
    }
    int run = (tid == 0) ? 0 : part[tid - 1];
    #pragma unroll
    for (int q = 0; q < 10; ++q) {
        int i = base + q;
        if (i < NN) { g_off[i] = run; run += g_deg[i]; }
    }
    if (tid == 0) g_off[NN] = part[1023];
}

// 0d) fill CSR slots with src ids
__global__ void csr_fill_kernel(const int* __restrict__ es,
                                const int* __restrict__ ed) {
    int e = blockIdx.x * 256 + threadIdx.x;
    if (e < NE) {
        int d = ed[e];
        int pos = atomicAdd(&g_fill[d], 1);
        g_csr[g_off[d] + pos] = es[e];
    }
}

// ============================================================================
// 1) hw = h @ W (fp32 SIMT, 0.33 GFLOP — negligible)
__device__ __forceinline__ void load_tileT(const float* __restrict__ src,
                                           int row0, int maxrows,
                                           float* __restrict__ Ts) {
    int lane = threadIdx.x & 31, w = threadIdx.x >> 5;
    #pragma unroll
    for (int rr = 0; rr < 16; ++rr) {
        int r = w * 16 + rr;
        bool ok = (row0 + r < maxrows);
        const float* p = src + (size_t)(row0 + r) * NH;
        #pragma unroll
        for (int q = 0; q < 4; ++q) {
            int k = lane + 32 * q;
            Ts[k * TS_STRIDE + r] = ok ? p[k] : 0.0f;
        }
    }
}
__device__ __forceinline__ void load_tile_rowmajor(const float* __restrict__ src,
                                                   float* __restrict__ Ts) {
    int lane = threadIdx.x & 31, w = threadIdx.x >> 5;
    #pragma unroll
    for (int rr = 0; rr < 16; ++rr) {
        int k = w * 16 + rr;
        #pragma unroll
        for (int q = 0; q < 4; ++q) {
            int n = lane + 32 * q;
            Ts[k * TS_STRIDE + n] = src[k * NH + n];
        }
    }
}
extern "C" __global__ void gemm_hw_kernel(const float* __restrict__ h,
                                          const float* __restrict__ W) {
    extern __shared__ float smemf[];
    float* As = smemf;
    float* Bs = smemf + 128 * TS_STRIDE;
    int row0 = blockIdx.x * 128;
    load_tileT(h, row0, NN, As);
    load_tile_rowmajor(W, Bs);
    __syncthreads();
    int tx = threadIdx.x & 15, ty = threadIdx.x >> 4;
    float acc[8][8] = {};
    #pragma unroll 8
    for (int k = 0; k < 128; ++k) {
        float a[8], b[8];
        #pragma unroll
        for (int i = 0; i < 8; ++i) a[i] = As[k * TS_STRIDE + ty + 16 * i];
        #pragma unroll
        for (int j = 0; j < 8; ++j) b[j] = Bs[k * TS_STRIDE + tx + 16 * j];
        #pragma unroll
        for (int i = 0; i < 8; ++i)
            #pragma unroll
            for (int j = 0; j < 8; ++j)
                acc[i][j] = fmaf(a[i], b[j], acc[i][j]);
    }
    #pragma unroll
    for (int i = 0; i < 8; ++i) {
        int m = row0 + ty + 16 * i;
        if (m < NN)
            #pragma unroll
            for (int j = 0; j < 8; ++j)
                g_hw[(size_t)m * NH + tx + 16 * j] = acc[i][j];
    }
}

// ============================================================================
// 2) fused gather + bias + relu + bf16 hi/lo split. One block per node row.
extern "C" __global__ void gather_fuse_kernel(const float* __restrict__ b) {
    int node = blockIdx.x;           // 0..NPAD-1
    int c = threadIdx.x;             // 0..127
    size_t o = (size_t)node * NH + c;
    if (node >= NN) {                // zero-pad rows
        g_xhi[o] = __float2bfloat16(0.0f);
        g_xlo[o] = __float2bfloat16(0.0f);
        return;
    }
    int beg = g_off[node];
    int end = g_off[node + 1];
    float acc = 0.0f;
    int e = beg;
    // 4-way unrolled gather for MLP
    for (; e + 4 <= end; e += 4) {
        int s0 = g_csr[e], s1 = g_csr[e + 1], s2 = g_csr[e + 2], s3 = g_csr[e + 3];
        float v0 = g_hw[(size_t)s0 * NH + c];
        float v1 = g_hw[(size_t)s1 * NH + c];
        float v2 = g_hw[(size_t)s2 * NH + c];
        float v3 = g_hw[(size_t)s3 * NH + c];
        acc += (v0 + v1) + (v2 + v3);
    }
    for (; e < end; ++e)
        acc += g_hw[(size_t)g_csr[e] * NH + c];

    float v = acc + b[c];
    v = v > 0.0f ? v : 0.0f;
    __nv_bfloat16 hi = __float2bfloat16(v);
    float r = v - __bfloat162float(hi);
    g_xhi[o] = hi;
    g_xlo[o] = __float2bfloat16(r);
}

// ============================================================================
// 3) out = x @ x^T via HMMA bf16 hi/lo 3-split, fused k-loop, symmetric tiles.
#define TILE_BYTES (128 * XT_STRIDE * 2)            // 34816
#define SMEM_XXT_BYTES (4 * TILE_BYTES)             // 139264

__device__ __forceinline__ void load_bf16_tile_pad(const __nv_bfloat16* __restrict__ src,
                                                   int row0, char* __restrict__ dst) {
    int tid = threadIdx.x;  // 256 threads
    #pragma unroll
    for (int it = 0; it < 8; ++it) {
        int chunk = it * 256 + tid;        // 0..2047 (16B chunks: 16 per row)
        int row   = chunk >> 4;
        int c16   = chunk & 15;
        uint4 v = *(const uint4*)(src + (size_t)(row0 + row) * NH + c16 * 8);
        *(uint4*)(dst + row * (XT_STRIDE * 2) + c16 * 16) = v;
    }
}

__device__ __forceinline__ void mma_bf16(float d[4], uint32_t a0, uint32_t a1,
                                         uint32_t a2, uint32_t a3,
                                         uint32_t b0, uint32_t b1) {
    asm volatile(
        "mma.sync.aligned.m16n8k16.row.col.f32.bf16.bf16.f32 "
        "{%0,%1,%2,%3}, {%4,%5,%6,%7}, {%8,%9}, {%0,%1,%2,%3};"
        : "+f"(d[0]), "+f"(d[1]), "+f"(d[2]), "+f"(d[3])
        : "r"(a0), "r"(a1), "r"(a2), "r"(a3), "r"(b0), "r"(b1));
}

extern "C" __global__ void __launch_bounds__(256, 1)
xxt_mma_kernel(float* __restrict__ out) {
    int bxn = blockIdx.x, bym = blockIdx.y;
    if (bxn < bym) return;   // lower triangle via mirror
    bool diag = (bxn == bym);

    extern __shared__ char smem[];
    char* Ahi = smem;
    char* Alo = smem + TILE_BYTES;
    char* Bhi = smem + 2 * TILE_BYTES;
    char* Blo = smem + 3 * TILE_BYTES;

    load_bf16_tile_pad(g_xhi, bym * 128, Ahi);
    load_bf16_tile_pad(g_xlo, bym * 128, Alo);
    if (!diag) {
        load_bf16_tile_pad(g_xhi, bxn * 128, Bhi);
        load_bf16_tile_pad(g_xlo, bxn * 128, Blo);
    }
    const char* Bh = diag ? Ahi : Bhi;
    const char* Bl = diag ? Alo : Blo;
    __syncthreads();

    int tid = threadIdx.x, lane = tid & 31, wid = tid >> 5;
    int wm = wid & 1;        // 0..1 -> 64 rows each
    int wn = wid >> 1;       // 0..3 -> 32 cols each
    int frow = lane >> 2;    // 0..7
    int fcol = 2 * (lane & 3);

    float acc[4][4][4] = {};

    #pragma unroll
    for (int k0 = 0; k0 < 8; ++k0) {
        int kc = 16 * k0 + fcol;
        // B fragments (hi + lo) for all 4 j
        uint32_t bh[4][2], bl[4][2];
        #pragma unroll
        for (int j = 0; j < 4; ++j) {
            int n = wn * 32 + j * 8 + frow;
            const char* ph = Bh + n * (XT_STRIDE * 2) + kc * 2;
            const char* pl = Bl + n * (XT_STRIDE * 2) + kc * 2;
            bh[j][0] = *(const uint32_t*)(ph);
            bh[j][1] = *(const uint32_t*)(ph + 16);
            bl[j][0] = *(const uint32_t*)(pl);
            bl[j][1] = *(const uint32_t*)(pl + 16);
        }
        #pragma unroll
        for (int i = 0; i < 4; ++i) {
            int r = wm * 64 + i * 16 + frow;
            const char* ph = Ahi + r * (XT_STRIDE * 2) + kc * 2;
            const char* pl = Alo + r * (XT_STRIDE * 2) + kc * 2;
            uint32_t ah0 = *(const uint32_t*)(ph);
            uint32_t ah1 = *(const uint32_t*)(ph + 8 * (XT_STRIDE * 2));
            uint32_t ah2 = *(const uint32_t*)(ph + 16);
            uint32_t ah3 = *(const uint32_t*)(ph + 8 * (XT_STRIDE * 2) + 16);
            uint32_t al0 = *(const uint32_t*)(pl);
            uint32_t al1 = *(const uint32_t*)(pl + 8 * (XT_STRIDE * 2));
            uint32_t al2 = *(const uint32_t*)(pl + 16);
            uint32_t al3 = *(const uint32_t*)(pl + 8 * (XT_STRIDE * 2) + 16);
            #pragma unroll
            for (int j = 0; j < 4; ++j) {
                mma_bf16(acc[i][j], ah0, ah1, ah2, ah3, bh[j][0], bh[j][1]);
                mma_bf16(acc[i][j], ah0, ah1, ah2, ah3, bl[j][0], bl[j][1]);
                mma_bf16(acc[i][j], al0, al1, al2, al3, bh[j][0], bh[j][1]);
            }
        }
    }

    int m0 = bym * 128, n0 = bxn * 128;

    // ---- direct store of the main tile from fragments (float2 = 32B sectors)
    bool edge = (n0 + 127 >= NN) || (m0 + 127 >= NN);   // only tile(s) touching 10000
    #pragma unroll
    for (int i = 0; i < 4; ++i) {
        int r = wm * 64 + i * 16 + frow;
        #pragma unroll
        for (int j = 0; j < 4; ++j) {
            int c = wn * 32 + j * 8 + fcol;
            if (!edge) {
                *(float2*)&out[(size_t)(m0 + r) * NN + n0 + c] =
                    make_float2(acc[i][j][0], acc[i][j][1]);
                *(float2*)&out[(size_t)(m0 + r + 8) * NN + n0 + c] =
                    make_float2(acc[i][j][2], acc[i][j][3]);
            } else {
                int m1 = m0 + r, m2 = m0 + r + 8, n = n0 + c;
                if (m1 < NN) {
                    if (n < NN)     out[(size_t)m1 * NN + n]     = acc[i][j][0];
                    if (n + 1 < NN) out[(size_t)m1 * NN + n + 1] = acc[i][j][1];
                }
                if (m2 < NN) {
                    if (n < NN)     out[(size_t)m2 * NN + n]     = acc[i][j][2];
                    if (n + 1 < NN) out[(size_t)m2 * NN + n + 1] = acc[i][j][3];
                }
            }
        }
    }

    // ---- mirror store C[n][m] via SMEM transpose stage (off-diagonal only)
    if (!diag) {
        __syncthreads();   // done with tiles; reuse smem as stage
        float* stage = (float*)smem;   // 128 x 129 f32
        #pragma unroll
        for (int i = 0; i < 4; ++i) {
            int r = wm * 64 + i * 16 + frow;
            #pragma unroll
            for (int j = 0; j < 4; ++j) {
                int c = wn * 32 + j * 8 + fcol;
                stage[r * TS_STRIDE + c]           = acc[i][j][0];
                stage[r * TS_STRIDE + c + 1]       = acc[i][j][1];
                stage[(r + 8) * TS_STRIDE + c]     = acc[i][j][2];
                stage[(r + 8) * TS_STRIDE + c + 1] = acc[i][j][3];
            }
        }
        __syncthreads();

        int rsub = tid >> 5;          // 0..7
        int cc = (tid & 31) << 2;     // 0..124 step 4
        #pragma unroll 4
        for (int it = 0; it < 16; ++it) {
            int r2 = it * 8 + rsub;        // local n
            int n = n0 + r2;
            if (n < NN) {
                float4 v;
                v.x = stage[(cc)     * TS_STRIDE + r2];
                v.y = stage[(cc + 1) * TS_STRIDE + r2];
                v.z = stage[(cc + 2) * TS_STRIDE + r2];
                v.w = stage[(cc + 3) * TS_STRIDE + r2];
                // mirror implies bym <= 77 -> m0 + cc + 3 < NN always
                *(float4*)&out[(size_t)n * NN + m0 + cc] = v;
            }
        }
    }
}

// ============================================================================
extern "C" void kernel_launch(void* const* d_in, const int* in_sizes, int n_in,
                              void* d_out, int out_size) {
    const float* h  = (const float*)d_in[0];
    const float* W  = (const float*)d_in[1];
    const float* b  = (const float*)d_in[2];
    const int*   es = (const int*)d_in[3];
    const int*   ed = (const int*)d_in[4];
    float*       out = (float*)d_out;

    const size_t smem_hw = (size_t)2 * 128 * TS_STRIDE * sizeof(float);
    cudaFuncSetAttribute(gemm_hw_kernel,
                         cudaFuncAttributeMaxDynamicSharedMemorySize, (int)smem_hw);
    cudaFuncSetAttribute(xxt_mma_kernel,
                         cudaFuncAttributeMaxDynamicSharedMemorySize, SMEM_XXT_BYTES);

    // CSR build (independent of hw gemm; cheap)
    csr_zero_kernel<<<(NN + 255) / 256, 256>>>();
    csr_count_kernel<<<(NE + 255) / 256, 256>>>(ed);
    csr_scan_kernel<<<1, 1024>>>();
    csr_fill_kernel<<<(NE + 255) / 256, 256>>>(es, ed);

    gemm_hw_kernel<<<(NN + 127) / 128, 256, smem_hw>>>(h, W);
    gather_fuse_kernel<<<NPAD, 128>>>(b);

    dim3 grid(79, 79);
    xxt_mma_kernel<<<grid, 256, SMEM_XXT_BYTES>>>(out);
}

// round 5
// speedup vs baseline: 2.2704x; 1.1181x over previous
#include <cuda_runtime.h>
#include <cuda_bf16.h>
#include <cstdint>

#define NN 10000
#define NE 320000
#define NH 128
#define NPAD 10112            // 79 * 128, zero-padded rows
#define TS_STRIDE 129         // f32 stage stride
#define XT_STRIDE 136         // bf16 tile stride: 272B/row == 16 mod 128 -> conflict-free

// ---------------- scratch (__device__ globals) -------------------------------
__device__ float g_hw[(size_t)NN * NH];
__device__ __nv_bfloat16 g_xhi[(size_t)NPAD * NH];
__device__ __nv_bfloat16 g_xlo[(size_t)NPAD * NH];
__device__ int g_deg[NN];
__device__ int g_off[NN + 1];
__device__ int g_fill[NN];
__device__ int g_csr[NE];

// ============================================================================
// CSR build
__global__ void csr_zero_kernel() {
    int i = blockIdx.x * 256 + threadIdx.x;
    if (i < NN) { g_deg[i] = 0; g_fill[i] = 0; }
}
__global__ void csr_count_kernel(const int* __restrict__ ed) {
    int e = blockIdx.x * 256 + threadIdx.x;
    if (e < NE) atomicAdd(&g_deg[ed[e]], 1);
}
__global__ void csr_scan_kernel() {
    __shared__ int part[1024];
    int tid = threadIdx.x;
    int base = tid * 10;
    int s = 0;
    #pragma unroll
    for (int q = 0; q < 10; ++q) { int i = base + q; if (i < NN) s += g_deg[i]; }
    part[tid] = s;
    __syncthreads();
    #pragma unroll
    for (int off = 1; off < 1024; off <<= 1) {
        int v = (tid >= off) ? part[tid - off] : 0;
        __syncthreads();
        part[tid] += v;
        __syncthreads();
    }
    int run = (tid == 0) ? 0 : part[tid - 1];
    #pragma unroll
    for (int q = 0; q < 10; ++q) {
        int i = base + q;
        if (i < NN) { g_off[i] = run; run += g_deg[i]; }
    }
    if (tid == 0) g_off[NN] = part[1023];
}
__global__ void csr_fill_kernel(const int* __restrict__ es,
                                const int* __restrict__ ed) {
    int e = blockIdx.x * 256 + threadIdx.x;
    if (e < NE) {
        int d = ed[e];
        int pos = atomicAdd(&g_fill[d], 1);
        g_csr[g_off[d] + pos] = es[e];
    }
}

// ============================================================================
// hw = h @ W (fp32 SIMT, small)
__device__ __forceinline__ void load_tileT(const float* __restrict__ src,
                                           int row0, int maxrows,
                                           float* __restrict__ Ts) {
    int lane = threadIdx.x & 31, w = threadIdx.x >> 5;
    #pragma unroll
    for (int rr = 0; rr < 16; ++rr) {
        int r = w * 16 + rr;
        bool ok = (row0 + r < maxrows);
        const float* p = src + (size_t)(row0 + r) * NH;
        #pragma unroll
        for (int q = 0; q < 4; ++q) {
            int k = lane + 32 * q;
            Ts[k * TS_STRIDE + r] = ok ? p[k] : 0.0f;
        }
    }
}
__device__ __forceinline__ void load_tile_rowmajor(const float* __restrict__ src,
                                                   float* __restrict__ Ts) {
    int lane = threadIdx.x & 31, w = threadIdx.x >> 5;
    #pragma unroll
    for (int rr = 0; rr < 16; ++rr) {
        int k = w * 16 + rr;
        #pragma unroll
        for (int q = 0; q < 4; ++q) {
            int n = lane + 32 * q;
            Ts[k * TS_STRIDE + n] = src[k * NH + n];
        }
    }
}
extern "C" __global__ void gemm_hw_kernel(const float* __restrict__ h,
                                          const float* __restrict__ W) {
    extern __shared__ float smemf[];
    float* As = smemf;
    float* Bs = smemf + 128 * TS_STRIDE;
    int row0 = blockIdx.x * 128;
    load_tileT(h, row0, NN, As);
    load_tile_rowmajor(W, Bs);
    __syncthreads();
    int tx = threadIdx.x & 15, ty = threadIdx.x >> 4;
    float acc[8][8] = {};
    #pragma unroll 8
    for (int k = 0; k < 128; ++k) {
        float a[8], b[8];
        #pragma unroll
        for (int i = 0; i < 8; ++i) a[i] = As[k * TS_STRIDE + ty + 16 * i];
        #pragma unroll
        for (int j = 0; j < 8; ++j) b[j] = Bs[k * TS_STRIDE + tx + 16 * j];
        #pragma unroll
        for (int i = 0; i < 8; ++i)
            #pragma unroll
            for (int j = 0; j < 8; ++j)
                acc[i][j] = fmaf(a[i], b[j], acc[i][j]);
    }
    #pragma unroll
    for (int i = 0; i < 8; ++i) {
        int m = row0 + ty + 16 * i;
        if (m < NN)
            #pragma unroll
            for (int j = 0; j < 8; ++j)
                g_hw[(size_t)m * NH + tx + 16 * j] = acc[i][j];
    }
}

// ============================================================================
// fused gather + bias + relu + bf16 hi/lo split
extern "C" __global__ void gather_fuse_kernel(const float* __restrict__ b) {
    int node = blockIdx.x;
    int c = threadIdx.x;
    size_t o = (size_t)node * NH + c;
    if (node >= NN) {
        g_xhi[o] = __float2bfloat16(0.0f);
        g_xlo[o] = __float2bfloat16(0.0f);
        return;
    }
    int beg = g_off[node];
    int end = g_off[node + 1];
    float acc = 0.0f;
    int e = beg;
    for (; e + 4 <= end; e += 4) {
        int s0 = g_csr[e], s1 = g_csr[e + 1], s2 = g_csr[e + 2], s3 = g_csr[e + 3];
        float v0 = g_hw[(size_t)s0 * NH + c];
        float v1 = g_hw[(size_t)s1 * NH + c];
        float v2 = g_hw[(size_t)s2 * NH + c];
        float v3 = g_hw[(size_t)s3 * NH + c];
        acc += (v0 + v1) + (v2 + v3);
    }
    for (; e < end; ++e)
        acc += g_hw[(size_t)g_csr[e] * NH + c];

    float v = acc + b[c];
    v = v > 0.0f ? v : 0.0f;
    __nv_bfloat16 hi = __float2bfloat16(v);
    float r = v - __bfloat162float(hi);
    g_xhi[o] = hi;
    g_xlo[o] = __float2bfloat16(r);
}

// ============================================================================
// xxt: HMMA bf16 hi/lo 3-split, 3-slot smem (occ 2), ldmatrix fragment loads
#define TILE_BYTES (128 * XT_STRIDE * 2)            // 34816
#define SMEM_XXT_BYTES (3 * TILE_BYTES)             // 104448 -> 2 CTAs/SM

__device__ __forceinline__ uint32_t smem_u32_of(const void* p) {
    uint32_t a;
    asm("{ .reg .u64 t; cvta.to.shared.u64 t, %1; cvt.u32.u64 %0, t; }"
        : "=r"(a) : "l"(p));
    return a;
}
__device__ __forceinline__ void ldsm_x4(uint32_t r[4], uint32_t addr) {
    asm volatile("ldmatrix.sync.aligned.m8n8.x4.shared.b16 {%0,%1,%2,%3}, [%4];"
                 : "=r"(r[0]), "=r"(r[1]), "=r"(r[2]), "=r"(r[3]) : "r"(addr));
}
__device__ __forceinline__ void load_bf16_tile_pad(const __nv_bfloat16* __restrict__ src,
                                                   int row0, char* __restrict__ dst) {
    int tid = threadIdx.x;  // 256 threads
    #pragma unroll
    for (int it = 0; it < 8; ++it) {
        int chunk = it * 256 + tid;
        int row   = chunk >> 4;
        int c16   = chunk & 15;
        uint4 v = *(const uint4*)(src + (size_t)(row0 + row) * NH + c16 * 8);
        *(uint4*)(dst + row * (XT_STRIDE * 2) + c16 * 16) = v;
    }
}
__device__ __forceinline__ void mma_bf16(float d[4], const uint32_t a[4],
                                         uint32_t b0, uint32_t b1) {
    asm volatile(
        "mma.sync.aligned.m16n8k16.row.col.f32.bf16.bf16.f32 "
        "{%0,%1,%2,%3}, {%4,%5,%6,%7}, {%8,%9}, {%0,%1,%2,%3};"
        : "+f"(d[0]), "+f"(d[1]), "+f"(d[2]), "+f"(d[3])
        : "r"(a[0]), "r"(a[1]), "r"(a[2]), "r"(a[3]), "r"(b0), "r"(b1));
}

extern "C" __global__ void __launch_bounds__(256, 2)
xxt_mma_kernel(float* __restrict__ out) {
    int bxn = blockIdx.x, bym = blockIdx.y;
    if (bxn < bym) return;
    bool diag = (bxn == bym);

    extern __shared__ char smem[];
    char* slotA = smem;                  // A_hi, later A_lo (off-diag)
    char* slotB1 = smem + TILE_BYTES;    // B_hi (off-diag) / A_lo (diag)
    char* slotB2 = smem + 2 * TILE_BYTES;// B_lo (off-diag only)

    load_bf16_tile_pad(g_xhi, bym * 128, slotA);
    if (diag) {
        load_bf16_tile_pad(g_xlo, bym * 128, slotB1);
    } else {
        load_bf16_tile_pad(g_xhi, bxn * 128, slotB1);
        load_bf16_tile_pad(g_xlo, bxn * 128, slotB2);
    }
    __syncthreads();

    int tid = threadIdx.x, lane = tid & 31, wid = tid >> 5;
    int wm = wid & 1;        // 64-row half
    int wn = wid >> 1;       // 32-col quarter
    int frow = lane >> 2;
    int fcol = 2 * (lane & 3);

    // ldmatrix lane offsets (bytes)
    const int RS = XT_STRIDE * 2;  // 272
    uint32_t laneA = (uint32_t)((lane & 15) * RS + (lane >> 4) * 16);
    uint32_t laneB = (uint32_t)((((lane >> 4) & 1) * 8 + (lane & 7)) * RS
                                + ((lane >> 3) & 1) * 16);
    uint32_t uA  = smem_u32_of(slotA);
    uint32_t uB1 = smem_u32_of(slotB1);
    uint32_t uB2 = smem_u32_of(slotB2);

    float acc[4][4][4] = {};

    // ---- fused passes: A_hi * B_hi^T  +  A_hi * B_lo^T
    {
        uint32_t bHi = diag ? uA : uB1;     // hi tile of columns
        uint32_t bLo = diag ? uB1 : uB2;    // lo tile of columns
        #pragma unroll
        for (int k0 = 0; k0 < 8; ++k0) {
            uint32_t kb = k0 * 32;
            uint32_t b1f[2][4], b2f[2][4];
            #pragma unroll
            for (int jp = 0; jp < 2; ++jp) {
                uint32_t nb = (uint32_t)((wn * 32 + jp * 16) * RS) + kb;
                ldsm_x4(b1f[jp], bHi + laneB + nb);
                ldsm_x4(b2f[jp], bLo + laneB + nb);
            }
            #pragma unroll
            for (int i = 0; i < 4; ++i) {
                uint32_t a[4];
                ldsm_x4(a, uA + laneA + (uint32_t)((wm * 64 + i * 16) * RS) + kb);
                #pragma unroll
                for (int jp = 0; jp < 2; ++jp) {
                    mma_bf16(acc[i][2 * jp],     a, b1f[jp][0], b1f[jp][1]);
                    mma_bf16(acc[i][2 * jp + 1], a, b1f[jp][2], b1f[jp][3]);
                    mma_bf16(acc[i][2 * jp],     a, b2f[jp][0], b2f[jp][1]);
                    mma_bf16(acc[i][2 * jp + 1], a, b2f[jp][2], b2f[jp][3]);
                }
            }
        }
    }

    // ---- pass 3: A_lo * B_hi^T
    uint32_t uAlo, uBhi;
    if (diag) {
        uAlo = uB1;    // lo already resident
        uBhi = uA;
    } else {
        __syncthreads();                        // done reading slotA (hi)
        load_bf16_tile_pad(g_xlo, bym * 128, slotA);
        __syncthreads();
        uAlo = uA;
        uBhi = uB1;
    }
    #pragma unroll
    for (int k0 = 0; k0 < 8; ++k0) {
        uint32_t kb = k0 * 32;
        uint32_t bf[2][4];
        #pragma unroll
        for (int jp = 0; jp < 2; ++jp)
            ldsm_x4(bf[jp], uBhi + laneB + (uint32_t)((wn * 32 + jp * 16) * RS) + kb);
        #pragma unroll
        for (int i = 0; i < 4; ++i) {
            uint32_t a[4];
            ldsm_x4(a, uAlo + laneA + (uint32_t)((wm * 64 + i * 16) * RS) + kb);
            #pragma unroll
            for (int jp = 0; jp < 2; ++jp) {
                mma_bf16(acc[i][2 * jp],     a, bf[jp][0], bf[jp][1]);
                mma_bf16(acc[i][2 * jp + 1], a, bf[jp][2], bf[jp][3]);
            }
        }
    }

    int m0 = bym * 128, n0 = bxn * 128;

    // ---- direct store of main tile from fragments (float2)
    bool edge = (n0 + 127 >= NN) || (m0 + 127 >= NN);
    #pragma unroll
    for (int i = 0; i < 4; ++i) {
        int r = wm * 64 + i * 16 + frow;
        #pragma unroll
        for (int j = 0; j < 4; ++j) {
            int c = wn * 32 + j * 8 + fcol;
            if (!edge) {
                *(float2*)&out[(size_t)(m0 + r) * NN + n0 + c] =
                    make_float2(acc[i][j][0], acc[i][j][1]);
                *(float2*)&out[(size_t)(m0 + r + 8) * NN + n0 + c] =
                    make_float2(acc[i][j][2], acc[i][j][3]);
            } else {
                int m1 = m0 + r, m2 = m0 + r + 8, n = n0 + c;
                if (m1 < NN) {
                    if (n < NN)     out[(size_t)m1 * NN + n]     = acc[i][j][0];
                    if (n + 1 < NN) out[(size_t)m1 * NN + n + 1] = acc[i][j][1];
                }
                if (m2 < NN) {
                    if (n < NN)     out[(size_t)m2 * NN + n]     = acc[i][j][2];
                    if (n + 1 < NN) out[(size_t)m2 * NN + n + 1] = acc[i][j][3];
                }
            }
        }
    }

    // ---- mirror store via SMEM transpose stage (off-diagonal only)
    if (!diag) {
        __syncthreads();
        float* stage = (float*)smem;   // 128 x 129 f32 = 66048 B < 104448
        #pragma unroll
        for (int i = 0; i < 4; ++i) {
            int r = wm * 64 + i * 16 + frow;
            #pragma unroll
            for (int j = 0; j < 4; ++j) {
                int c = wn * 32 + j * 8 + fcol;
                stage[r * TS_STRIDE + c]           = acc[i][j][0];
                stage[r * TS_STRIDE + c + 1]       = acc[i][j][1];
                stage[(r + 8) * TS_STRIDE + c]     = acc[i][j][2];
                stage[(r + 8) * TS_STRIDE + c + 1] = acc[i][j][3];
            }
        }
        __syncthreads();

        int rsub = tid >> 5;
        int cc = (tid & 31) << 2;
        #pragma unroll 4
        for (int it = 0; it < 16; ++it) {
            int r2 = it * 8 + rsub;
            int n = n0 + r2;
            if (n < NN) {
                float4 v;
                v.x = stage[(cc)     * TS_STRIDE + r2];
                v.y = stage[(cc + 1) * TS_STRIDE + r2];
                v.z = stage[(cc + 2) * TS_STRIDE + r2];
                v.w = stage[(cc + 3) * TS_STRIDE + r2];
                *(float4*)&out[(size_t)n * NN + m0 + cc] = v;
            }
        }
    }
}

// ============================================================================
extern "C" void kernel_launch(void* const* d_in, const int* in_sizes, int n_in,
                              void* d_out, int out_size) {
    const float* h  = (const float*)d_in[0];
    const float* W  = (const float*)d_in[1];
    const float* b  = (const float*)d_in[2];
    const int*   es = (const int*)d_in[3];
    const int*   ed = (const int*)d_in[4];
    float*       out = (float*)d_out;

    const size_t smem_hw = (size_t)2 * 128 * TS_STRIDE * sizeof(float);
    cudaFuncSetAttribute(gemm_hw_kernel,
                         cudaFuncAttributeMaxDynamicSharedMemorySize, (int)smem_hw);
    cudaFuncSetAttribute(xxt_mma_kernel,
                         cudaFuncAttributeMaxDynamicSharedMemorySize, SMEM_XXT_BYTES);

    csr_zero_kernel<<<(NN + 255) / 256, 256>>>();
    csr_count_kernel<<<(NE + 255) / 256, 256>>>(ed);
    csr_scan_kernel<<<1, 1024>>>();
    csr_fill_kernel<<<(NE + 255) / 256, 256>>>(es, ed);

    gemm_hw_kernel<<<(NN + 127) / 128, 256, smem_hw>>>(h, W);
    gather_fuse_kernel<<<NPAD, 128>>>(b);

    dim3 grid(79, 79);
    xxt_mma_kernel<<<grid, 256, SMEM_XXT_BYTES>>>(out);
}